// round 4
// baseline (speedup 1.0000x reference)
#include <cuda_runtime.h>
#include <cuda_bf16.h>
#include <cstdint>
#include <math.h>

#define GFD   4096
#define DH    1024
#define BATCH 32
#define TK    196
#define BT    (BATCH * TK)   // 6272

// Output layout in d_out (float): c_img[32,1024] | coverage_new[32,196,1] | alpha[32,196,1]
#define OUT_C      0
#define OUT_COV    (BATCH * DH)
#define OUT_ALPHA  (BATCH * DH + BT)

// ============================ scratch (__device__ globals) ============================
__device__ __align__(1024) __nv_bfloat16 g_WgH[GFD * GFD];
__device__ __align__(1024) __nv_bfloat16 g_WgL[GFD * GFD];
__device__ __align__(1024) __nv_bfloat16 g_gfH[BT * GFD];
__device__ __align__(1024) __nv_bfloat16 g_gfL[BT * GFD];
__device__ __align__(1024) __nv_bfloat16 g_GsTH[DH * GFD];   // Gs^T  [DH, GFD]
__device__ __align__(1024) __nv_bfloat16 g_GsTL[DH * GFD];
__device__ __align__(1024) float         g_W2[GFD * DH];     // Wg@Gs [GFD, DH]
__device__ __align__(1024) __nv_bfloat16 g_W2TH[DH * GFD];   // W2^T  [DH, GFD]
__device__ __align__(1024) __nv_bfloat16 g_W2TL[DH * GFD];
__device__ __align__(1024) __nv_bfloat16 g_WgsTH[DH * DH];   // Wgs^T [DH, DH]
__device__ __align__(1024) __nv_bfloat16 g_WgsTL[DH * DH];
__device__ __align__(1024) float         g_gstar[BT * DH];
__device__ __align__(1024) __nv_bfloat16 g_gsH[BT * DH];
__device__ __align__(1024) __nv_bfloat16 g_gsL[BT * DH];
__device__ float g_b2[DH];
__device__ float g_dec[BATCH * DH];
__device__ float g_scores[BT];
__device__ float g_alpha[BT];

// ============================ helpers ============================
__device__ __forceinline__ uint32_t smem_u32(const void* p) {
    uint32_t a;
    asm("{ .reg .u64 t; cvta.to.shared.u64 t, %1; cvt.u32.u64 %0, t; }" : "=r"(a) : "l"(p));
    return a;
}
__device__ __forceinline__ void ldsm4(uint32_t* r, uint32_t addr) {
    asm volatile("ldmatrix.sync.aligned.m8n8.x4.shared.b16 {%0,%1,%2,%3}, [%4];"
                 : "=r"(r[0]), "=r"(r[1]), "=r"(r[2]), "=r"(r[3]) : "r"(addr));
}
__device__ __forceinline__ void mma16816(float* c, const uint32_t* a, const uint32_t* b) {
    asm volatile("mma.sync.aligned.m16n8k16.row.col.f32.bf16.bf16.f32 "
                 "{%0,%1,%2,%3}, {%4,%5,%6,%7}, {%8,%9}, {%0,%1,%2,%3};"
                 : "+f"(c[0]), "+f"(c[1]), "+f"(c[2]), "+f"(c[3])
                 : "r"(a[0]), "r"(a[1]), "r"(a[2]), "r"(a[3]), "r"(b[0]), "r"(b[1]));
}
__device__ __forceinline__ uint32_t swz(uint32_t off) {   // SW128: bits[6:4] ^= bits[9:7]
    return off ^ ((off >> 3) & 0x70);
}

// ============================ split-bf16 mma.sync GEMM ============================
// C[M,N] = Ah@Bh^T + Ah@Bl^T + Al@Bh^T, fp32 accum. A:[M,K] row-major, B:[N,K] row-major.
// CTA tile 128x128, K-tile 64, 3-stage cp.async pipeline, 8 warps, warp tile 64x32.
#define KTILE     64
#define TILE_B    16384                 // one 128x64 bf16 tile
#define STG_B     (4 * TILE_B)          // AH AL BH BL = 64 KB
#define NSTAGE    3
#define SM_AH(s)  ((s) * STG_B)
#define SM_AL(s)  (SM_AH(s) + TILE_B)
#define SM_BH(s)  (SM_AH(s) + 2 * TILE_B)
#define SM_BL(s)  (SM_AH(s) + 3 * TILE_B)
#define GEMM_SMEM (NSTAGE * STG_B)      // 192 KB

__device__ __forceinline__ void issue_stage(
    uint32_t sb, int s, int kt,
    const __nv_bfloat16* __restrict__ Ah, const __nv_bfloat16* __restrict__ Al,
    const __nv_bfloat16* __restrict__ Bh, const __nv_bfloat16* __restrict__ Bl,
    int K, int bm, int bn, int tid)
{
    const int k0 = kt * KTILE;
#pragma unroll
    for (int i = 0; i < 4; i++) {
        int idx = tid + i * 256;
        int r = idx >> 3, c = idx & 7;
        uint32_t so = swz((uint32_t)(r * 128 + c * 16));
        size_t goA = (size_t)(bm + r) * K + k0 + c * 8;
        size_t goB = (size_t)(bn + r) * K + k0 + c * 8;
        asm volatile("cp.async.cg.shared.global [%0], [%1], 16;" :: "r"(sb + SM_AH(s) + so), "l"(Ah + goA) : "memory");
        asm volatile("cp.async.cg.shared.global [%0], [%1], 16;" :: "r"(sb + SM_AL(s) + so), "l"(Al + goA) : "memory");
        asm volatile("cp.async.cg.shared.global [%0], [%1], 16;" :: "r"(sb + SM_BH(s) + so), "l"(Bh + goB) : "memory");
        asm volatile("cp.async.cg.shared.global [%0], [%1], 16;" :: "r"(sb + SM_BL(s) + so), "l"(Bl + goB) : "memory");
    }
    asm volatile("cp.async.commit_group;" ::: "memory");
}

// mode 0: outF = D                                   (W2)
// mode 1: outF = D + bias; emit bf16 hi/lo           (g_star)
// mode 2: scores[m] += sum_n tanh(D + dec + cov)*v   (fused attention scores)
__global__ void __launch_bounds__(256, 1) gemm_mma(
    const __nv_bfloat16* __restrict__ Ah, const __nv_bfloat16* __restrict__ Al,
    const __nv_bfloat16* __restrict__ Bh, const __nv_bfloat16* __restrict__ Bl,
    int K, int KT, int mode,
    float* __restrict__ outF, const float* __restrict__ bias,
    __nv_bfloat16* __restrict__ outH, __nv_bfloat16* __restrict__ outL,
    const float* __restrict__ dec, const float* __restrict__ cov,
    const float* __restrict__ v, float* __restrict__ scores)
{
    extern __shared__ char smem[];
    const uint32_t sb  = smem_u32(smem);
    const int tid  = threadIdx.x;
    const int wid  = tid >> 5, lane = tid & 31;
    const int wm   = wid & 1,  wn   = wid >> 1;     // warp grid 2(m) x 4(n)
    const int bm   = blockIdx.y * 128, bn = blockIdx.x * 128;

    float acc[4][4][4];
#pragma unroll
    for (int a = 0; a < 4; a++)
#pragma unroll
        for (int b = 0; b < 4; b++)
#pragma unroll
            for (int c = 0; c < 4; c++) acc[a][b][c] = 0.f;

    // per-lane ldmatrix offsets (within-tile)
    const uint32_t a_row  = (uint32_t)(wm * 64 + (lane & 15));                         // + mi*16
    const uint32_t a_kofs = (uint32_t)(((lane >> 4) & 1) * 16);                        // + kk*32
    const uint32_t b_row  = (uint32_t)(wn * 32 + (lane & 7) + ((lane >> 4) & 1) * 8);  // + nq*16
    const uint32_t b_kofs = (uint32_t)(((lane >> 3) & 1) * 16);                        // + kk*32

    // prologue: 2 stages in flight
    issue_stage(sb, 0, 0, Ah, Al, Bh, Bl, K, bm, bn, tid);
    issue_stage(sb, 1, 1, Ah, Al, Bh, Bl, K, bm, bn, tid);

    for (int kt = 0; kt < KT; kt++) {
        if (kt + 2 < KT)
            asm volatile("cp.async.wait_group 1;" ::: "memory");
        else
            asm volatile("cp.async.wait_group 0;" ::: "memory");
        __syncthreads();   // stage kt%3 ready for all; all warps done with stage (kt-1)%3

        if (kt + 2 < KT)
            issue_stage(sb, (kt + 2) % NSTAGE, kt + 2, Ah, Al, Bh, Bl, K, bm, bn, tid);

        const int s = kt % NSTAGE;
        const uint32_t aH = sb + SM_AH(s), aL = sb + SM_AL(s);
        const uint32_t bH = sb + SM_BH(s), bL = sb + SM_BL(s);
#pragma unroll
        for (int kk = 0; kk < 4; kk++) {
            uint32_t fAh[4][4], fAl[4][4], fBh[2][4], fBl[2][4];
#pragma unroll
            for (int mi = 0; mi < 4; mi++) {
                uint32_t off = swz((a_row + mi * 16) * 128 + kk * 32 + a_kofs);
                ldsm4(fAh[mi], aH + off);
                ldsm4(fAl[mi], aL + off);
            }
#pragma unroll
            for (int nq = 0; nq < 2; nq++) {
                uint32_t off = swz((b_row + nq * 16) * 128 + kk * 32 + b_kofs);
                ldsm4(fBh[nq], bH + off);
                ldsm4(fBl[nq], bL + off);
            }
#pragma unroll
            for (int mi = 0; mi < 4; mi++)
#pragma unroll
                for (int nt = 0; nt < 4; nt++) {
                    const uint32_t* ph = &fBh[nt >> 1][(nt & 1) * 2];
                    const uint32_t* pl = &fBl[nt >> 1][(nt & 1) * 2];
                    mma16816(acc[mi][nt], fAh[mi], ph);
                    mma16816(acc[mi][nt], fAh[mi], pl);
                    mma16816(acc[mi][nt], fAl[mi], ph);
                }
        }
    }

    // ---------------- epilogue (register accumulators, vectorized stores) ----------------
    const int g = lane >> 2, tig = lane & 3;
#pragma unroll
    for (int mi = 0; mi < 4; mi++) {
#pragma unroll
        for (int h = 0; h < 2; h++) {
            const int m = bm + wm * 64 + mi * 16 + g + h * 8;
            float rsum = 0.f, cv = 0.f;
            int bofs = 0;
            if (mode == 2) { cv = cov[m]; bofs = (m / TK) * DH; }
#pragma unroll
            for (int nt = 0; nt < 4; nt++) {
                const int n = bn + wn * 32 + nt * 8 + 2 * tig;
                float x0 = acc[mi][nt][h * 2 + 0];
                float x1 = acc[mi][nt][h * 2 + 1];
                if (mode == 0) {
                    *(float2*)&outF[(size_t)m * DH + n] = make_float2(x0, x1);
                } else if (mode == 1) {
                    x0 += bias[n];  x1 += bias[n + 1];
                    *(float2*)&outF[(size_t)m * DH + n] = make_float2(x0, x1);
                    __nv_bfloat16 h0 = __float2bfloat16(x0), h1 = __float2bfloat16(x1);
                    *(__nv_bfloat162*)&outH[(size_t)m * DH + n] = __halves2bfloat162(h0, h1);
                    *(__nv_bfloat162*)&outL[(size_t)m * DH + n] = __halves2bfloat162(
                        __float2bfloat16(x0 - __bfloat162float(h0)),
                        __float2bfloat16(x1 - __bfloat162float(h1)));
                } else {
                    rsum += tanhf(x0 + dec[bofs + n] + cv) * v[n];
                    rsum += tanhf(x1 + dec[bofs + n + 1] + cv) * v[n + 1];
                }
            }
            if (mode == 2) {
                rsum += __shfl_xor_sync(0xffffffffu, rsum, 1);
                rsum += __shfl_xor_sync(0xffffffffu, rsum, 2);
                if (tig == 0) atomicAdd(&scores[m], rsum);
            }
        }
    }
}

// ============================ conversion kernels ============================
__global__ void __launch_bounds__(256) csplit(
    const float4* __restrict__ in, __nv_bfloat162* __restrict__ oh,
    __nv_bfloat162* __restrict__ ol, int n4)
{
    int i = blockIdx.x * 256 + threadIdx.x;
    if (i >= n4) return;
    float4 x = in[i];
    __nv_bfloat16 h0 = __float2bfloat16(x.x), h1 = __float2bfloat16(x.y);
    __nv_bfloat16 h2 = __float2bfloat16(x.z), h3 = __float2bfloat16(x.w);
    oh[2 * i]     = __halves2bfloat162(h0, h1);
    oh[2 * i + 1] = __halves2bfloat162(h2, h3);
    ol[2 * i]     = __halves2bfloat162(__float2bfloat16(x.x - __bfloat162float(h0)),
                                       __float2bfloat16(x.y - __bfloat162float(h1)));
    ol[2 * i + 1] = __halves2bfloat162(__float2bfloat16(x.z - __bfloat162float(h2)),
                                       __float2bfloat16(x.w - __bfloat162float(h3)));
}

// out[C,R] = split(in[R,C]^T)
__global__ void __launch_bounds__(256) tconv(
    const float* __restrict__ in, __nv_bfloat16* __restrict__ oh,
    __nv_bfloat16* __restrict__ ol, int R, int C)
{
    __shared__ float t[32][33];
    const int bx = blockIdx.x * 32, by = blockIdx.y * 32;
    const int x = threadIdx.x & 31, y = threadIdx.x >> 5;
#pragma unroll
    for (int i = 0; i < 32; i += 8)
        t[y + i][x] = in[(size_t)(by + y + i) * C + bx + x];
    __syncthreads();
#pragma unroll
    for (int i = 0; i < 32; i += 8) {
        float val = t[x][y + i];
        __nv_bfloat16 h = __float2bfloat16(val);
        size_t o = (size_t)(bx + y + i) * R + by + x;
        oh[o] = h;
        ol[o] = __float2bfloat16(val - __bfloat162float(h));
    }
}

// ============================ small kernels ============================
__global__ void __launch_bounds__(256) b2_kernel(
    const float* __restrict__ bg, const float* __restrict__ Gs,
    const float* __restrict__ bgs, float* __restrict__ b2)
{
    const int j = blockIdx.x * 256 + threadIdx.x;
    float s = bgs[j];
#pragma unroll 8
    for (int i = 0; i < GFD; i++) s += bg[i] * Gs[(size_t)i * DH + j];
    b2[j] = s;
}

__global__ void __launch_bounds__(256) dec_kernel(
    const float* __restrict__ s_t_hat, const float* __restrict__ Wdec,
    const float* __restrict__ bdec, float* __restrict__ dec)
{
    const int idx = blockIdx.x * 256 + threadIdx.x;
    const int b = idx >> 10, j = idx & (DH - 1);
    float s = bdec[j];
#pragma unroll 8
    for (int k = 0; k < DH; k++) s += s_t_hat[b * DH + k] * Wdec[(size_t)k * DH + j];
    dec[idx] = s;
}

__global__ void __launch_bounds__(256) softmax_kernel(
    const float* __restrict__ scores, const float* __restrict__ cov,
    float* __restrict__ alpha, float* __restrict__ out)
{
    const int b = blockIdx.x, t = threadIdx.x;
    __shared__ float red[8];
    __shared__ float smax, ssum;
    float sv = (t < TK) ? scores[b * TK + t] : -3.4e38f;

    float m = sv;
#pragma unroll
    for (int o = 16; o > 0; o >>= 1) m = fmaxf(m, __shfl_xor_sync(0xffffffffu, m, o));
    if ((t & 31) == 0) red[t >> 5] = m;
    __syncthreads();
    if (t < 8) {
        m = red[t];
#pragma unroll
        for (int o = 4; o > 0; o >>= 1) m = fmaxf(m, __shfl_xor_sync(0xffu, m, o));
        if (t == 0) smax = m;
    }
    __syncthreads();

    float e = (t < TK) ? expf(sv - smax) : 0.f;
    float su = e;
#pragma unroll
    for (int o = 16; o > 0; o >>= 1) su += __shfl_xor_sync(0xffffffffu, su, o);
    if ((t & 31) == 0) red[t >> 5] = su;
    __syncthreads();
    if (t < 8) {
        su = red[t];
#pragma unroll
        for (int o = 4; o > 0; o >>= 1) su += __shfl_xor_sync(0xffu, su, o);
        if (t == 0) ssum = su;
    }
    __syncthreads();

    if (t < TK) {
        const float a = e / ssum;
        alpha[b * TK + t] = a;
        out[OUT_ALPHA + b * TK + t] = a;
        out[OUT_COV + b * TK + t] = cov[b * TK + t] + a;
    }
}

__global__ void __launch_bounds__(256) cimg_kernel(
    const float* __restrict__ gstar, const float* __restrict__ alpha,
    float* __restrict__ out)
{
    const int b = blockIdx.y;
    const int d = blockIdx.x * 256 + threadIdx.x;
    __shared__ float sal[TK];
    if (threadIdx.x < TK) sal[threadIdx.x] = alpha[b * TK + threadIdx.x];
    __syncthreads();
    float s = 0.f;
#pragma unroll 4
    for (int t = 0; t < TK; t++)
        s += sal[t] * gstar[((size_t)(b * TK + t)) * DH + d];
    out[OUT_C + b * DH + d] = s;
}

// ============================ launch ============================
extern "C" void kernel_launch(void* const* d_in, const int* in_sizes, int n_in,
                              void* d_out, int out_size)
{
    const float* gf   = (const float*)d_in[0];
    const float* sth  = (const float*)d_in[1];
    const float* cov  = (const float*)d_in[2];
    const float* Wg   = (const float*)d_in[3];
    const float* bg   = (const float*)d_in[4];
    const float* Gs   = (const float*)d_in[5];
    const float* bgs  = (const float*)d_in[6];
    const float* Wgs  = (const float*)d_in[7];
    const float* Wdec = (const float*)d_in[8];
    const float* bdec = (const float*)d_in[9];
    const float* v    = (const float*)d_in[10];
    float* out = (float*)d_out;

    __nv_bfloat16 *WgH, *WgL, *gfH, *gfL, *GsTH, *GsTL, *W2TH, *W2TL, *WgsTH, *WgsTL, *gsH, *gsL;
    float *W2p, *gstarp, *b2p, *decp, *scoresp, *alphap;
    cudaGetSymbolAddress((void**)&WgH, g_WgH);     cudaGetSymbolAddress((void**)&WgL, g_WgL);
    cudaGetSymbolAddress((void**)&gfH, g_gfH);     cudaGetSymbolAddress((void**)&gfL, g_gfL);
    cudaGetSymbolAddress((void**)&GsTH, g_GsTH);   cudaGetSymbolAddress((void**)&GsTL, g_GsTL);
    cudaGetSymbolAddress((void**)&W2p, g_W2);
    cudaGetSymbolAddress((void**)&W2TH, g_W2TH);   cudaGetSymbolAddress((void**)&W2TL, g_W2TL);
    cudaGetSymbolAddress((void**)&WgsTH, g_WgsTH); cudaGetSymbolAddress((void**)&WgsTL, g_WgsTL);
    cudaGetSymbolAddress((void**)&gstarp, g_gstar);
    cudaGetSymbolAddress((void**)&gsH, g_gsH);     cudaGetSymbolAddress((void**)&gsL, g_gsL);
    cudaGetSymbolAddress((void**)&b2p, g_b2);      cudaGetSymbolAddress((void**)&decp, g_dec);
    cudaGetSymbolAddress((void**)&scoresp, g_scores);
    cudaGetSymbolAddress((void**)&alphap, g_alpha);

    cudaFuncSetAttribute(gemm_mma, cudaFuncAttributeMaxDynamicSharedMemorySize, GEMM_SMEM);

    // --- conversions ---
    csplit<<<(GFD * GFD / 4 + 255) / 256, 256>>>((const float4*)Wg,
        (__nv_bfloat162*)WgH, (__nv_bfloat162*)WgL, GFD * GFD / 4);
    csplit<<<(BT * GFD / 4 + 255) / 256, 256>>>((const float4*)gf,
        (__nv_bfloat162*)gfH, (__nv_bfloat162*)gfL, BT * GFD / 4);
    {   dim3 g(DH / 32, GFD / 32);  tconv<<<g, 256>>>(Gs, GsTH, GsTL, GFD, DH); }
    {   dim3 g(DH / 32, DH / 32);   tconv<<<g, 256>>>(Wgs, WgsTH, WgsTL, DH, DH); }

    // --- small precomputes ---
    b2_kernel<<<DH / 256, 256>>>(bg, Gs, bgs, b2p);
    dec_kernel<<<(BATCH * DH) / 256, 256>>>(sth, Wdec, bdec, decp);
    cudaMemsetAsync(scoresp, 0, BT * sizeof(float));

    // --- GEMM1: W2 = Wg @ Gs   [4096,1024], K=4096 ---
    {
        dim3 grid(DH / 128, GFD / 128);
        gemm_mma<<<grid, 256, GEMM_SMEM>>>(WgH, WgL, GsTH, GsTL, GFD, GFD / KTILE, 0,
            W2p, nullptr, nullptr, nullptr, nullptr, nullptr, nullptr, nullptr);
    }
    {   dim3 g(DH / 32, GFD / 32);  tconv<<<g, 256>>>(W2p, W2TH, W2TL, GFD, DH); }

    // --- GEMM2: g_star = gf @ W2 + b2   [6272,1024], K=4096 ---
    {
        dim3 grid(DH / 128, BT / 128);
        gemm_mma<<<grid, 256, GEMM_SMEM>>>(gfH, gfL, W2TH, W2TL, GFD, GFD / KTILE, 1,
            gstarp, b2p, gsH, gsL, nullptr, nullptr, nullptr, nullptr);
    }

    // --- GEMM3 (fused): scores = tanh(g_star@Wgs + dec + cov) . v   K=1024 ---
    {
        dim3 grid(DH / 128, BT / 128);
        gemm_mma<<<grid, 256, GEMM_SMEM>>>(gsH, gsL, WgsTH, WgsTL, DH, DH / KTILE, 2,
            nullptr, nullptr, nullptr, nullptr, decp, cov, v, scoresp);
    }

    // --- softmax + context ---
    softmax_kernel<<<BATCH, 256>>>(scoresp, cov, alphap, out);
    {   dim3 grid(DH / 256, BATCH);  cimg_kernel<<<grid, 256>>>(gstarp, alphap, out); }
}

// round 5
// speedup vs baseline: 1.0458x; 1.0458x over previous
#include <cuda_runtime.h>
#include <cuda_bf16.h>
#include <cstdint>
#include <math.h>

#define GFD   4096
#define DH    1024
#define BATCH 32
#define TK    196
#define BT    (BATCH * TK)   // 6272

// Output layout in d_out (float): c_img[32,1024] | coverage_new[32,196,1] | alpha[32,196,1]
#define OUT_C      0
#define OUT_COV    (BATCH * DH)
#define OUT_ALPHA  (BATCH * DH + BT)

// ============================ scratch (__device__ globals) ============================
__device__ __align__(1024) __nv_bfloat16 g_WgH[GFD * GFD];
__device__ __align__(1024) __nv_bfloat16 g_WgL[GFD * GFD];
__device__ __align__(1024) __nv_bfloat16 g_gfH[BT * GFD];
__device__ __align__(1024) __nv_bfloat16 g_gfL[BT * GFD];
__device__ __align__(1024) __nv_bfloat16 g_GsTH[DH * GFD];   // Gs^T  [DH, GFD]
__device__ __align__(1024) __nv_bfloat16 g_GsTL[DH * GFD];
__device__ __align__(1024) float         g_W2[GFD * DH];     // Wg@Gs [GFD, DH]
__device__ __align__(1024) __nv_bfloat16 g_W2TH[DH * GFD];   // W2^T  [DH, GFD]
__device__ __align__(1024) __nv_bfloat16 g_W2TL[DH * GFD];
__device__ __align__(1024) __nv_bfloat16 g_WgsTH[DH * DH];   // Wgs^T [DH, DH]
__device__ __align__(1024) __nv_bfloat16 g_WgsTL[DH * DH];
__device__ __align__(1024) float         g_gstar[BT * DH];
__device__ __align__(1024) __nv_bfloat16 g_gsH[BT * DH];
__device__ __align__(1024) __nv_bfloat16 g_gsL[BT * DH];
__device__ float g_b2[DH];
__device__ float g_dec[BATCH * DH];
__device__ float g_scores[BT];
__device__ float g_alpha[BT];

// ============================ helpers ============================
__device__ __forceinline__ uint32_t smem_u32(const void* p) {
    uint32_t a;
    asm("{ .reg .u64 t; cvta.to.shared.u64 t, %1; cvt.u32.u64 %0, t; }" : "=r"(a) : "l"(p));
    return a;
}
__device__ __forceinline__ void ldsm4(uint32_t* r, uint32_t addr) {
    asm volatile("ldmatrix.sync.aligned.m8n8.x4.shared.b16 {%0,%1,%2,%3}, [%4];"
                 : "=r"(r[0]), "=r"(r[1]), "=r"(r[2]), "=r"(r[3]) : "r"(addr));
}
__device__ __forceinline__ void mma16816(float* c, const uint32_t* a, const uint32_t* b) {
    asm volatile("mma.sync.aligned.m16n8k16.row.col.f32.bf16.bf16.f32 "
                 "{%0,%1,%2,%3}, {%4,%5,%6,%7}, {%8,%9}, {%0,%1,%2,%3};"
                 : "+f"(c[0]), "+f"(c[1]), "+f"(c[2]), "+f"(c[3])
                 : "r"(a[0]), "r"(a[1]), "r"(a[2]), "r"(a[3]), "r"(b[0]), "r"(b[1]));
}
__device__ __forceinline__ uint32_t swz(uint32_t off) {   // SW128: bits[6:4] ^= bits[9:7]
    return off ^ ((off >> 3) & 0x70);
}

// ============================ split-bf16 mma.sync GEMM ============================
// C[M,N] = Ah@Bh^T + Ah@Bl^T + Al@Bh^T, fp32 accum. A:[M,K] row-major, B:[N,K] row-major.
// CTA tile 128x128, K-tile 64, double-buffered cp.async, 8 warps, warp tile 64x32.
// MMA issue is pass-reordered: 16 independent accumulators per pass (no RAW chains).
#define KTILE     64
#define TILE_B    16384                 // one 128x64 bf16 tile
#define STG_B     (4 * TILE_B)          // AH AL BH BL
#define SM_AH(s)  ((s) * STG_B)
#define SM_AL(s)  (SM_AH(s) + TILE_B)
#define SM_BH(s)  (SM_AH(s) + 2 * TILE_B)
#define SM_BL(s)  (SM_AH(s) + 3 * TILE_B)
#define GEMM_SMEM (2 * STG_B)           // 128 KB

__device__ __forceinline__ void issue_stage(
    uint32_t sb, int s, int kt,
    const __nv_bfloat16* __restrict__ Ah, const __nv_bfloat16* __restrict__ Al,
    const __nv_bfloat16* __restrict__ Bh, const __nv_bfloat16* __restrict__ Bl,
    int K, int bm, int bn, int tid)
{
    const int k0 = kt * KTILE;
#pragma unroll
    for (int i = 0; i < 4; i++) {
        int idx = tid + i * 256;
        int r = idx >> 3, c = idx & 7;
        uint32_t so = swz((uint32_t)(r * 128 + c * 16));
        size_t goA = (size_t)(bm + r) * K + k0 + c * 8;
        size_t goB = (size_t)(bn + r) * K + k0 + c * 8;
        asm volatile("cp.async.cg.shared.global [%0], [%1], 16;" :: "r"(sb + SM_AH(s) + so), "l"(Ah + goA) : "memory");
        asm volatile("cp.async.cg.shared.global [%0], [%1], 16;" :: "r"(sb + SM_AL(s) + so), "l"(Al + goA) : "memory");
        asm volatile("cp.async.cg.shared.global [%0], [%1], 16;" :: "r"(sb + SM_BH(s) + so), "l"(Bh + goB) : "memory");
        asm volatile("cp.async.cg.shared.global [%0], [%1], 16;" :: "r"(sb + SM_BL(s) + so), "l"(Bl + goB) : "memory");
    }
    asm volatile("cp.async.commit_group;" ::: "memory");
}

// mode 0: outF = D                                   (W2)
// mode 1: outF = D + bias; emit bf16 hi/lo           (g_star)
// mode 2: scores[m] += sum_n tanh(D + dec + cov)*v   (fused attention scores)
__global__ void __launch_bounds__(256, 1) gemm_mma(
    const __nv_bfloat16* __restrict__ Ah, const __nv_bfloat16* __restrict__ Al,
    const __nv_bfloat16* __restrict__ Bh, const __nv_bfloat16* __restrict__ Bl,
    int K, int KT, int mode,
    float* __restrict__ outF, const float* __restrict__ bias,
    __nv_bfloat16* __restrict__ outH, __nv_bfloat16* __restrict__ outL,
    const float* __restrict__ dec, const float* __restrict__ cov,
    const float* __restrict__ v, float* __restrict__ scores)
{
    extern __shared__ char smem[];
    const uint32_t sb  = smem_u32(smem);
    const int tid  = threadIdx.x;
    const int wid  = tid >> 5, lane = tid & 31;
    const int wm   = wid & 1,  wn   = wid >> 1;     // warp grid 2(m) x 4(n)
    const int bm   = blockIdx.y * 128, bn = blockIdx.x * 128;

    float acc[4][4][4];
#pragma unroll
    for (int a = 0; a < 4; a++)
#pragma unroll
        for (int b = 0; b < 4; b++)
#pragma unroll
            for (int c = 0; c < 4; c++) acc[a][b][c] = 0.f;

    // per-lane ldmatrix offsets (within-tile)
    const uint32_t a_row  = (uint32_t)(wm * 64 + (lane & 15));                         // + mi*16
    const uint32_t a_kofs = (uint32_t)(((lane >> 4) & 1) * 16);                        // + kk*32
    const uint32_t b_row  = (uint32_t)(wn * 32 + (lane & 7) + ((lane >> 4) & 1) * 8);  // + nq*16
    const uint32_t b_kofs = (uint32_t)(((lane >> 3) & 1) * 16);                        // + kk*32

    issue_stage(sb, 0, 0, Ah, Al, Bh, Bl, K, bm, bn, tid);

    for (int kt = 0; kt < KT; kt++) {
        const int s = kt & 1;
        if (kt + 1 < KT) {
            issue_stage(sb, s ^ 1, kt + 1, Ah, Al, Bh, Bl, K, bm, bn, tid);
            asm volatile("cp.async.wait_group 1;" ::: "memory");
        } else {
            asm volatile("cp.async.wait_group 0;" ::: "memory");
        }
        __syncthreads();

        const uint32_t aH = sb + SM_AH(s), aL = sb + SM_AL(s);
        const uint32_t bH = sb + SM_BH(s), bL = sb + SM_BL(s);
#pragma unroll
        for (int kk = 0; kk < 4; kk++) {
            uint32_t fAh[4][4], fAl[4][4], fBh[2][4], fBl[2][4];
            // ---- pass 1: Ah x Bh  (16 independent accumulators) ----
#pragma unroll
            for (int mi = 0; mi < 4; mi++) {
                uint32_t off = swz((a_row + mi * 16) * 128 + kk * 32 + a_kofs);
                ldsm4(fAh[mi], aH + off);
            }
#pragma unroll
            for (int nq = 0; nq < 2; nq++) {
                uint32_t off = swz((b_row + nq * 16) * 128 + kk * 32 + b_kofs);
                ldsm4(fBh[nq], bH + off);
            }
#pragma unroll
            for (int mi = 0; mi < 4; mi++)
#pragma unroll
                for (int nt = 0; nt < 4; nt++)
                    mma16816(acc[mi][nt], fAh[mi], &fBh[nt >> 1][(nt & 1) * 2]);

            // ---- pass 2: Ah x Bl ----
#pragma unroll
            for (int nq = 0; nq < 2; nq++) {
                uint32_t off = swz((b_row + nq * 16) * 128 + kk * 32 + b_kofs);
                ldsm4(fBl[nq], bL + off);
            }
#pragma unroll
            for (int mi = 0; mi < 4; mi++)
#pragma unroll
                for (int nt = 0; nt < 4; nt++)
                    mma16816(acc[mi][nt], fAh[mi], &fBl[nt >> 1][(nt & 1) * 2]);

            // ---- pass 3: Al x Bh ----
#pragma unroll
            for (int mi = 0; mi < 4; mi++) {
                uint32_t off = swz((a_row + mi * 16) * 128 + kk * 32 + a_kofs);
                ldsm4(fAl[mi], aL + off);
            }
#pragma unroll
            for (int mi = 0; mi < 4; mi++)
#pragma unroll
                for (int nt = 0; nt < 4; nt++)
                    mma16816(acc[mi][nt], fAl[mi], &fBh[nt >> 1][(nt & 1) * 2]);
        }
        __syncthreads();
    }

    // ---------------- epilogue (register accumulators, vectorized stores) ----------------
    const int g = lane >> 2, tig = lane & 3;
#pragma unroll
    for (int mi = 0; mi < 4; mi++) {
#pragma unroll
        for (int h = 0; h < 2; h++) {
            const int m = bm + wm * 64 + mi * 16 + g + h * 8;
            float rsum = 0.f, cv = 0.f;
            int bofs = 0;
            if (mode == 2) { cv = cov[m]; bofs = (m / TK) * DH; }
#pragma unroll
            for (int nt = 0; nt < 4; nt++) {
                const int n = bn + wn * 32 + nt * 8 + 2 * tig;
                float x0 = acc[mi][nt][h * 2 + 0];
                float x1 = acc[mi][nt][h * 2 + 1];
                if (mode == 0) {
                    *(float2*)&outF[(size_t)m * DH + n] = make_float2(x0, x1);
                } else if (mode == 1) {
                    x0 += bias[n];  x1 += bias[n + 1];
                    *(float2*)&outF[(size_t)m * DH + n] = make_float2(x0, x1);
                    __nv_bfloat16 h0 = __float2bfloat16(x0), h1 = __float2bfloat16(x1);
                    *(__nv_bfloat162*)&outH[(size_t)m * DH + n] = __halves2bfloat162(h0, h1);
                    *(__nv_bfloat162*)&outL[(size_t)m * DH + n] = __halves2bfloat162(
                        __float2bfloat16(x0 - __bfloat162float(h0)),
                        __float2bfloat16(x1 - __bfloat162float(h1)));
                } else {
                    rsum += tanhf(x0 + dec[bofs + n] + cv) * v[n];
                    rsum += tanhf(x1 + dec[bofs + n + 1] + cv) * v[n + 1];
                }
            }
            if (mode == 2) {
                rsum += __shfl_xor_sync(0xffffffffu, rsum, 1);
                rsum += __shfl_xor_sync(0xffffffffu, rsum, 2);
                if (tig == 0) atomicAdd(&scores[m], rsum);
            }
        }
    }
}

// ============================ conversion kernels ============================
__global__ void __launch_bounds__(256) csplit(
    const float4* __restrict__ in, __nv_bfloat162* __restrict__ oh,
    __nv_bfloat162* __restrict__ ol, int n4)
{
    int i = blockIdx.x * 256 + threadIdx.x;
    if (i >= n4) return;
    float4 x = in[i];
    __nv_bfloat16 h0 = __float2bfloat16(x.x), h1 = __float2bfloat16(x.y);
    __nv_bfloat16 h2 = __float2bfloat16(x.z), h3 = __float2bfloat16(x.w);
    oh[2 * i]     = __halves2bfloat162(h0, h1);
    oh[2 * i + 1] = __halves2bfloat162(h2, h3);
    ol[2 * i]     = __halves2bfloat162(__float2bfloat16(x.x - __bfloat162float(h0)),
                                       __float2bfloat16(x.y - __bfloat162float(h1)));
    ol[2 * i + 1] = __halves2bfloat162(__float2bfloat16(x.z - __bfloat162float(h2)),
                                       __float2bfloat16(x.w - __bfloat162float(h3)));
}

// out[C,R] = split(in[R,C]^T)
__global__ void __launch_bounds__(256) tconv(
    const float* __restrict__ in, __nv_bfloat16* __restrict__ oh,
    __nv_bfloat16* __restrict__ ol, int R, int C)
{
    __shared__ float t[32][33];
    const int bx = blockIdx.x * 32, by = blockIdx.y * 32;
    const int x = threadIdx.x & 31, y = threadIdx.x >> 5;
#pragma unroll
    for (int i = 0; i < 32; i += 8)
        t[y + i][x] = in[(size_t)(by + y + i) * C + bx + x];
    __syncthreads();
#pragma unroll
    for (int i = 0; i < 32; i += 8) {
        float val = t[x][y + i];
        __nv_bfloat16 h = __float2bfloat16(val);
        size_t o = (size_t)(bx + y + i) * R + by + x;
        oh[o] = h;
        ol[o] = __float2bfloat16(val - __bfloat162float(h));
    }
}

// ============================ small kernels ============================
__global__ void __launch_bounds__(256) b2_kernel(
    const float* __restrict__ bg, const float* __restrict__ Gs,
    const float* __restrict__ bgs, float* __restrict__ b2)
{
    const int j = blockIdx.x * 256 + threadIdx.x;
    float s = bgs[j];
#pragma unroll 8
    for (int i = 0; i < GFD; i++) s += bg[i] * Gs[(size_t)i * DH + j];
    b2[j] = s;
}

__global__ void __launch_bounds__(256) dec_kernel(
    const float* __restrict__ s_t_hat, const float* __restrict__ Wdec,
    const float* __restrict__ bdec, float* __restrict__ dec)
{
    const int idx = blockIdx.x * 256 + threadIdx.x;
    const int b = idx >> 10, j = idx & (DH - 1);
    float s = bdec[j];
#pragma unroll 8
    for (int k = 0; k < DH; k++) s += s_t_hat[b * DH + k] * Wdec[(size_t)k * DH + j];
    dec[idx] = s;
}

__global__ void __launch_bounds__(256) softmax_kernel(
    const float* __restrict__ scores, const float* __restrict__ cov,
    float* __restrict__ alpha, float* __restrict__ out)
{
    const int b = blockIdx.x, t = threadIdx.x;
    __shared__ float red[8];
    __shared__ float smax, ssum;
    float sv = (t < TK) ? scores[b * TK + t] : -3.4e38f;

    float m = sv;
#pragma unroll
    for (int o = 16; o > 0; o >>= 1) m = fmaxf(m, __shfl_xor_sync(0xffffffffu, m, o));
    if ((t & 31) == 0) red[t >> 5] = m;
    __syncthreads();
    if (t < 8) {
        m = red[t];
#pragma unroll
        for (int o = 4; o > 0; o >>= 1) m = fmaxf(m, __shfl_xor_sync(0xffu, m, o));
        if (t == 0) smax = m;
    }
    __syncthreads();

    float e = (t < TK) ? expf(sv - smax) : 0.f;
    float su = e;
#pragma unroll
    for (int o = 16; o > 0; o >>= 1) su += __shfl_xor_sync(0xffffffffu, su, o);
    if ((t & 31) == 0) red[t >> 5] = su;
    __syncthreads();
    if (t < 8) {
        su = red[t];
#pragma unroll
        for (int o = 4; o > 0; o >>= 1) su += __shfl_xor_sync(0xffu, su, o);
        if (t == 0) ssum = su;
    }
    __syncthreads();

    if (t < TK) {
        const float a = e / ssum;
        alpha[b * TK + t] = a;
        out[OUT_ALPHA + b * TK + t] = a;
        out[OUT_COV + b * TK + t] = cov[b * TK + t] + a;
    }
}

__global__ void __launch_bounds__(256) cimg_kernel(
    const float* __restrict__ gstar, const float* __restrict__ alpha,
    float* __restrict__ out)
{
    const int b = blockIdx.y;
    const int d = blockIdx.x * 256 + threadIdx.x;
    __shared__ float sal[TK];
    if (threadIdx.x < TK) sal[threadIdx.x] = alpha[b * TK + threadIdx.x];
    __syncthreads();
    float s = 0.f;
#pragma unroll 4
    for (int t = 0; t < TK; t++)
        s += sal[t] * gstar[((size_t)(b * TK + t)) * DH + d];
    out[OUT_C + b * DH + d] = s;
}

// ============================ launch ============================
extern "C" void kernel_launch(void* const* d_in, const int* in_sizes, int n_in,
                              void* d_out, int out_size)
{
    const float* gf   = (const float*)d_in[0];
    const float* sth  = (const float*)d_in[1];
    const float* cov  = (const float*)d_in[2];
    const float* Wg   = (const float*)d_in[3];
    const float* bg   = (const float*)d_in[4];
    const float* Gs   = (const float*)d_in[5];
    const float* bgs  = (const float*)d_in[6];
    const float* Wgs  = (const float*)d_in[7];
    const float* Wdec = (const float*)d_in[8];
    const float* bdec = (const float*)d_in[9];
    const float* v    = (const float*)d_in[10];
    float* out = (float*)d_out;

    __nv_bfloat16 *WgH, *WgL, *gfH, *gfL, *GsTH, *GsTL, *W2TH, *W2TL, *WgsTH, *WgsTL, *gsH, *gsL;
    float *W2p, *gstarp, *b2p, *decp, *scoresp, *alphap;
    cudaGetSymbolAddress((void**)&WgH, g_WgH);     cudaGetSymbolAddress((void**)&WgL, g_WgL);
    cudaGetSymbolAddress((void**)&gfH, g_gfH);     cudaGetSymbolAddress((void**)&gfL, g_gfL);
    cudaGetSymbolAddress((void**)&GsTH, g_GsTH);   cudaGetSymbolAddress((void**)&GsTL, g_GsTL);
    cudaGetSymbolAddress((void**)&W2p, g_W2);
    cudaGetSymbolAddress((void**)&W2TH, g_W2TH);   cudaGetSymbolAddress((void**)&W2TL, g_W2TL);
    cudaGetSymbolAddress((void**)&WgsTH, g_WgsTH); cudaGetSymbolAddress((void**)&WgsTL, g_WgsTL);
    cudaGetSymbolAddress((void**)&gstarp, g_gstar);
    cudaGetSymbolAddress((void**)&gsH, g_gsH);     cudaGetSymbolAddress((void**)&gsL, g_gsL);
    cudaGetSymbolAddress((void**)&b2p, g_b2);      cudaGetSymbolAddress((void**)&decp, g_dec);
    cudaGetSymbolAddress((void**)&scoresp, g_scores);
    cudaGetSymbolAddress((void**)&alphap, g_alpha);

    cudaFuncSetAttribute(gemm_mma, cudaFuncAttributeMaxDynamicSharedMemorySize, GEMM_SMEM);

    // Launch order arranged so gemm1 lands on the ncu-captured slot.
    // (0) split Wg
    csplit<<<(GFD * GFD / 4 + 255) / 256, 256>>>((const float4*)Wg,
        (__nv_bfloat162*)WgH, (__nv_bfloat162*)WgL, GFD * GFD / 4);
    // (1) transpose+split Gs
    {   dim3 g(DH / 32, GFD / 32);  tconv<<<g, 256>>>(Gs, GsTH, GsTL, GFD, DH); }
    // (2) b2 = bg @ Gs + bgs
    b2_kernel<<<DH / 256, 256>>>(bg, Gs, bgs, b2p);
    // (3) GEMM1: W2 = Wg @ Gs   [4096,1024], K=4096
    {
        dim3 grid(DH / 128, GFD / 128);
        gemm_mma<<<grid, 256, GEMM_SMEM>>>(WgH, WgL, GsTH, GsTL, GFD, GFD / KTILE, 0,
            W2p, nullptr, nullptr, nullptr, nullptr, nullptr, nullptr, nullptr);
    }
    // (4) split gf
    csplit<<<(BT * GFD / 4 + 255) / 256, 256>>>((const float4*)gf,
        (__nv_bfloat162*)gfH, (__nv_bfloat162*)gfL, BT * GFD / 4);
    // (5) transpose+split W2
    {   dim3 g(DH / 32, GFD / 32);  tconv<<<g, 256>>>(W2p, W2TH, W2TL, GFD, DH); }
    // (6) GEMM2: g_star = gf @ W2 + b2   [6272,1024], K=4096
    {
        dim3 grid(DH / 128, BT / 128);
        gemm_mma<<<grid, 256, GEMM_SMEM>>>(gfH, gfL, W2TH, W2TL, GFD, GFD / KTILE, 1,
            gstarp, b2p, gsH, gsL, nullptr, nullptr, nullptr, nullptr);
    }
    // (7) transpose+split Wgs
    {   dim3 g(DH / 32, DH / 32);   tconv<<<g, 256>>>(Wgs, WgsTH, WgsTL, DH, DH); }
    // (8) dec = s_t_hat @ Wdec + bdec
    dec_kernel<<<(BATCH * DH) / 256, 256>>>(sth, Wdec, bdec, decp);
    // (9) zero scores
    cudaMemsetAsync(scoresp, 0, BT * sizeof(float));
    // (10) GEMM3 (fused): scores = tanh(g_star@Wgs + dec + cov) . v   K=1024
    {
        dim3 grid(DH / 128, BT / 128);
        gemm_mma<<<grid, 256, GEMM_SMEM>>>(gsH, gsL, WgsTH, WgsTL, DH, DH / KTILE, 2,
            nullptr, nullptr, nullptr, nullptr, decp, cov, v, scoresp);
    }
    // (11) softmax + outputs
    softmax_kernel<<<BATCH, 256>>>(scoresp, cov, alphap, out);
    // (12) context vector
    {   dim3 grid(DH / 256, BATCH);  cimg_kernel<<<grid, 256>>>(gstarp, alphap, out); }
}

// round 6
// speedup vs baseline: 1.0932x; 1.0453x over previous
#include <cuda_runtime.h>
#include <cuda_bf16.h>
#include <cstdint>
#include <math.h>

#define GFD   4096
#define DH    1024
#define BATCH 32
#define TK    196
#define BT    (BATCH * TK)   // 6272

// Output layout in d_out (float): c_img[32,1024] | coverage_new[32,196,1] | alpha[32,196,1]
#define OUT_C      0
#define OUT_COV    (BATCH * DH)
#define OUT_ALPHA  (BATCH * DH + BT)

// ============================ scratch (__device__ globals) ============================
__device__ __align__(1024) __nv_bfloat16 g_WgH[GFD * GFD];
__device__ __align__(1024) __nv_bfloat16 g_WgL[GFD * GFD];
__device__ __align__(1024) __nv_bfloat16 g_gfH[BT * GFD];
__device__ __align__(1024) __nv_bfloat16 g_gfL[BT * GFD];
__device__ __align__(1024) __nv_bfloat16 g_GsTH[DH * GFD];   // Gs^T  [DH, GFD]
__device__ __align__(1024) __nv_bfloat16 g_GsTL[DH * GFD];
__device__ __align__(1024) float         g_W2[GFD * DH];     // Wg@Gs [GFD, DH]
__device__ __align__(1024) __nv_bfloat16 g_W2TH[DH * GFD];   // W2^T  [DH, GFD]
__device__ __align__(1024) __nv_bfloat16 g_W2TL[DH * GFD];
__device__ __align__(1024) __nv_bfloat16 g_WgsTH[DH * DH];   // Wgs^T [DH, DH]
__device__ __align__(1024) __nv_bfloat16 g_WgsTL[DH * DH];
__device__ __align__(1024) float         g_gstar[BT * DH];
__device__ __align__(1024) __nv_bfloat16 g_gsH[BT * DH];
__device__ __align__(1024) __nv_bfloat16 g_gsL[BT * DH];
__device__ float g_b2[DH];
__device__ float g_dec[BATCH * DH];
__device__ float g_scores[BT];
__device__ float g_alpha[BT];

// ============================ helpers ============================
__device__ __forceinline__ uint32_t smem_u32(const void* p) {
    uint32_t a;
    asm("{ .reg .u64 t; cvta.to.shared.u64 t, %1; cvt.u32.u64 %0, t; }" : "=r"(a) : "l"(p));
    return a;
}
__device__ __forceinline__ void ldsm4(uint32_t* r, uint32_t addr) {
    asm volatile("ldmatrix.sync.aligned.m8n8.x4.shared.b16 {%0,%1,%2,%3}, [%4];"
                 : "=r"(r[0]), "=r"(r[1]), "=r"(r[2]), "=r"(r[3]) : "r"(addr));
}
__device__ __forceinline__ void mma16816(float* c, const uint32_t* a, const uint32_t* b) {
    asm volatile("mma.sync.aligned.m16n8k16.row.col.f32.bf16.bf16.f32 "
                 "{%0,%1,%2,%3}, {%4,%5,%6,%7}, {%8,%9}, {%0,%1,%2,%3};"
                 : "+f"(c[0]), "+f"(c[1]), "+f"(c[2]), "+f"(c[3])
                 : "r"(a[0]), "r"(a[1]), "r"(a[2]), "r"(a[3]), "r"(b[0]), "r"(b[1]));
}
__device__ __forceinline__ uint32_t swz(uint32_t off) {   // SW128: bits[6:4] ^= bits[9:7]
    return off ^ ((off >> 3) & 0x70);
}

// ============================ split-bf16 mma.sync GEMM ============================
// C[M,N] = Ah@Bh^T + Ah@Bl^T + Al@Bh^T, fp32 accum. A:[M,K] row-major, B:[N,K] row-major.
// CTA: 128 threads (4 warps, 2x2), CTA tile 128x64, K-tile 64, double-buffered cp.async.
// 2 CTAs/SM so one CTA's MMAs cover the other's barriers/loads/epilogue.
#define KTILE     64
#define A_TILE_B  16384                 // 128x64 bf16
#define B_TILE_B  8192                  // 64x64 bf16
#define STG_B     (2 * A_TILE_B + 2 * B_TILE_B)   // 48 KB
#define SM_AH(s)  ((s) * STG_B)
#define SM_AL(s)  (SM_AH(s) + A_TILE_B)
#define SM_BH(s)  (SM_AH(s) + 2 * A_TILE_B)
#define SM_BL(s)  (SM_AH(s) + 2 * A_TILE_B + B_TILE_B)
#define GEMM_SMEM (2 * STG_B)           // 96 KB

__device__ __forceinline__ void issue_stage(
    uint32_t sb, int s, int kt,
    const __nv_bfloat16* __restrict__ Ah, const __nv_bfloat16* __restrict__ Al,
    const __nv_bfloat16* __restrict__ Bh, const __nv_bfloat16* __restrict__ Bl,
    int K, int bm, int bn, int tid)
{
    const int k0 = kt * KTILE;
#pragma unroll
    for (int i = 0; i < 8; i++) {        // A: 128 rows x 8 cols(16B)
        int idx = tid + i * 128;
        int r = idx >> 3, c = idx & 7;
        uint32_t so = swz((uint32_t)(r * 128 + c * 16));
        size_t go = (size_t)(bm + r) * K + k0 + c * 8;
        asm volatile("cp.async.cg.shared.global [%0], [%1], 16;" :: "r"(sb + SM_AH(s) + so), "l"(Ah + go) : "memory");
        asm volatile("cp.async.cg.shared.global [%0], [%1], 16;" :: "r"(sb + SM_AL(s) + so), "l"(Al + go) : "memory");
    }
#pragma unroll
    for (int i = 0; i < 4; i++) {        // B: 64 rows x 8 cols(16B)
        int idx = tid + i * 128;
        int r = idx >> 3, c = idx & 7;
        uint32_t so = swz((uint32_t)(r * 128 + c * 16));
        size_t go = (size_t)(bn + r) * K + k0 + c * 8;
        asm volatile("cp.async.cg.shared.global [%0], [%1], 16;" :: "r"(sb + SM_BH(s) + so), "l"(Bh + go) : "memory");
        asm volatile("cp.async.cg.shared.global [%0], [%1], 16;" :: "r"(sb + SM_BL(s) + so), "l"(Bl + go) : "memory");
    }
    asm volatile("cp.async.commit_group;" ::: "memory");
}

// mode 0: outF = D                                   (W2)
// mode 1: outF = D + bias; emit bf16 hi/lo           (g_star)
// mode 2: scores[m] += sum_n tanh(D + dec + cov)*v   (fused attention scores)
__global__ void __launch_bounds__(128, 2) gemm_mma(
    const __nv_bfloat16* __restrict__ Ah, const __nv_bfloat16* __restrict__ Al,
    const __nv_bfloat16* __restrict__ Bh, const __nv_bfloat16* __restrict__ Bl,
    int K, int KT, int mode,
    float* __restrict__ outF, const float* __restrict__ bias,
    __nv_bfloat16* __restrict__ outH, __nv_bfloat16* __restrict__ outL,
    const float* __restrict__ dec, const float* __restrict__ cov,
    const float* __restrict__ v, float* __restrict__ scores)
{
    extern __shared__ char smem[];
    const uint32_t sb  = smem_u32(smem);
    const int tid  = threadIdx.x;
    const int wid  = tid >> 5, lane = tid & 31;
    const int wm   = wid & 1,  wn   = wid >> 1;     // warp grid 2(m) x 2(n)
    const int bm   = blockIdx.y * 128, bn = blockIdx.x * 64;

    float acc[4][4][4];
#pragma unroll
    for (int a = 0; a < 4; a++)
#pragma unroll
        for (int b = 0; b < 4; b++)
#pragma unroll
            for (int c = 0; c < 4; c++) acc[a][b][c] = 0.f;

    // per-lane ldmatrix offsets (within-tile)
    const uint32_t a_row  = (uint32_t)(wm * 64 + (lane & 15));                         // + mi*16
    const uint32_t a_kofs = (uint32_t)(((lane >> 4) & 1) * 16);                        // + kk*32
    const uint32_t b_row  = (uint32_t)(wn * 32 + (lane & 7) + ((lane >> 4) & 1) * 8);  // + nq*16
    const uint32_t b_kofs = (uint32_t)(((lane >> 3) & 1) * 16);                        // + kk*32

    issue_stage(sb, 0, 0, Ah, Al, Bh, Bl, K, bm, bn, tid);

    for (int kt = 0; kt < KT; kt++) {
        const int s = kt & 1;
        if (kt + 1 < KT) {
            issue_stage(sb, s ^ 1, kt + 1, Ah, Al, Bh, Bl, K, bm, bn, tid);
            asm volatile("cp.async.wait_group 1;" ::: "memory");
        } else {
            asm volatile("cp.async.wait_group 0;" ::: "memory");
        }
        __syncthreads();

        const uint32_t aH = sb + SM_AH(s), aL = sb + SM_AL(s);
        const uint32_t bH = sb + SM_BH(s), bL = sb + SM_BL(s);
#pragma unroll
        for (int kk = 0; kk < 4; kk++) {
            uint32_t fAh[4][4], fAl[4][4], fBh[2][4], fBl[2][4];
            // ---- pass 1: Ah x Bh (16 independent accumulators) ----
#pragma unroll
            for (int mi = 0; mi < 4; mi++) {
                uint32_t off = swz((a_row + mi * 16) * 128 + kk * 32 + a_kofs);
                ldsm4(fAh[mi], aH + off);
            }
#pragma unroll
            for (int nq = 0; nq < 2; nq++) {
                uint32_t off = swz((b_row + nq * 16) * 128 + kk * 32 + b_kofs);
                ldsm4(fBh[nq], bH + off);
            }
#pragma unroll
            for (int mi = 0; mi < 4; mi++)
#pragma unroll
                for (int nt = 0; nt < 4; nt++)
                    mma16816(acc[mi][nt], fAh[mi], &fBh[nt >> 1][(nt & 1) * 2]);

            // ---- pass 2: Ah x Bl ----
#pragma unroll
            for (int nq = 0; nq < 2; nq++) {
                uint32_t off = swz((b_row + nq * 16) * 128 + kk * 32 + b_kofs);
                ldsm4(fBl[nq], bL + off);
            }
#pragma unroll
            for (int mi = 0; mi < 4; mi++)
#pragma unroll
                for (int nt = 0; nt < 4; nt++)
                    mma16816(acc[mi][nt], fAh[mi], &fBl[nt >> 1][(nt & 1) * 2]);

            // ---- pass 3: Al x Bh ----
#pragma unroll
            for (int mi = 0; mi < 4; mi++) {
                uint32_t off = swz((a_row + mi * 16) * 128 + kk * 32 + a_kofs);
                ldsm4(fAl[mi], aL + off);
            }
#pragma unroll
            for (int mi = 0; mi < 4; mi++)
#pragma unroll
                for (int nt = 0; nt < 4; nt++)
                    mma16816(acc[mi][nt], fAl[mi], &fBh[nt >> 1][(nt & 1) * 2]);
        }
        __syncthreads();
    }

    // ---------------- epilogue (register accumulators, vectorized stores) ----------------
    const int g = lane >> 2, tig = lane & 3;
#pragma unroll
    for (int mi = 0; mi < 4; mi++) {
#pragma unroll
        for (int h = 0; h < 2; h++) {
            const int m = bm + wm * 64 + mi * 16 + g + h * 8;
            float rsum = 0.f, cv = 0.f;
            int bofs = 0;
            if (mode == 2) { cv = cov[m]; bofs = (m / TK) * DH; }
#pragma unroll
            for (int nt = 0; nt < 4; nt++) {
                const int n = bn + wn * 32 + nt * 8 + 2 * tig;
                float x0 = acc[mi][nt][h * 2 + 0];
                float x1 = acc[mi][nt][h * 2 + 1];
                if (mode == 0) {
                    *(float2*)&outF[(size_t)m * DH + n] = make_float2(x0, x1);
                } else if (mode == 1) {
                    x0 += bias[n];  x1 += bias[n + 1];
                    *(float2*)&outF[(size_t)m * DH + n] = make_float2(x0, x1);
                    __nv_bfloat16 h0 = __float2bfloat16(x0), h1 = __float2bfloat16(x1);
                    *(__nv_bfloat162*)&outH[(size_t)m * DH + n] = __halves2bfloat162(h0, h1);
                    *(__nv_bfloat162*)&outL[(size_t)m * DH + n] = __halves2bfloat162(
                        __float2bfloat16(x0 - __bfloat162float(h0)),
                        __float2bfloat16(x1 - __bfloat162float(h1)));
                } else {
                    rsum += tanhf(x0 + dec[bofs + n] + cv) * v[n];
                    rsum += tanhf(x1 + dec[bofs + n + 1] + cv) * v[n + 1];
                }
            }
            if (mode == 2) {
                rsum += __shfl_xor_sync(0xffffffffu, rsum, 1);
                rsum += __shfl_xor_sync(0xffffffffu, rsum, 2);
                if (tig == 0) atomicAdd(&scores[m], rsum);
            }
        }
    }
}

// ============================ conversion kernels ============================
__global__ void __launch_bounds__(256) csplit(
    const float4* __restrict__ in, __nv_bfloat162* __restrict__ oh,
    __nv_bfloat162* __restrict__ ol, int n4)
{
    int i = blockIdx.x * 256 + threadIdx.x;
    if (i >= n4) return;
    float4 x = in[i];
    __nv_bfloat16 h0 = __float2bfloat16(x.x), h1 = __float2bfloat16(x.y);
    __nv_bfloat16 h2 = __float2bfloat16(x.z), h3 = __float2bfloat16(x.w);
    oh[2 * i]     = __halves2bfloat162(h0, h1);
    oh[2 * i + 1] = __halves2bfloat162(h2, h3);
    ol[2 * i]     = __halves2bfloat162(__float2bfloat16(x.x - __bfloat162float(h0)),
                                       __float2bfloat16(x.y - __bfloat162float(h1)));
    ol[2 * i + 1] = __halves2bfloat162(__float2bfloat16(x.z - __bfloat162float(h2)),
                                       __float2bfloat16(x.w - __bfloat162float(h3)));
}

// out[C,R] = split(in[R,C]^T)
__global__ void __launch_bounds__(256) tconv(
    const float* __restrict__ in, __nv_bfloat16* __restrict__ oh,
    __nv_bfloat16* __restrict__ ol, int R, int C)
{
    __shared__ float t[32][33];
    const int bx = blockIdx.x * 32, by = blockIdx.y * 32;
    const int x = threadIdx.x & 31, y = threadIdx.x >> 5;
#pragma unroll
    for (int i = 0; i < 32; i += 8)
        t[y + i][x] = in[(size_t)(by + y + i) * C + bx + x];
    __syncthreads();
#pragma unroll
    for (int i = 0; i < 32; i += 8) {
        float val = t[x][y + i];
        __nv_bfloat16 h = __float2bfloat16(val);
        size_t o = (size_t)(bx + y + i) * R + by + x;
        oh[o] = h;
        ol[o] = __float2bfloat16(val - __bfloat162float(h));
    }
}

// ============================ small kernels ============================
__global__ void __launch_bounds__(256) b2_kernel(
    const float* __restrict__ bg, const float* __restrict__ Gs,
    const float* __restrict__ bgs, float* __restrict__ b2)
{
    const int j = blockIdx.x * 256 + threadIdx.x;
    float s = bgs[j];
#pragma unroll 8
    for (int i = 0; i < GFD; i++) s += bg[i] * Gs[(size_t)i * DH + j];
    b2[j] = s;
}

__global__ void __launch_bounds__(256) dec_kernel(
    const float* __restrict__ s_t_hat, const float* __restrict__ Wdec,
    const float* __restrict__ bdec, float* __restrict__ dec)
{
    const int idx = blockIdx.x * 256 + threadIdx.x;
    const int b = idx >> 10, j = idx & (DH - 1);
    float s = bdec[j];
#pragma unroll 8
    for (int k = 0; k < DH; k++) s += s_t_hat[b * DH + k] * Wdec[(size_t)k * DH + j];
    dec[idx] = s;
}

__global__ void __launch_bounds__(256) softmax_kernel(
    const float* __restrict__ scores, const float* __restrict__ cov,
    float* __restrict__ alpha, float* __restrict__ out)
{
    const int b = blockIdx.x, t = threadIdx.x;
    __shared__ float red[8];
    __shared__ float smax, ssum;
    float sv = (t < TK) ? scores[b * TK + t] : -3.4e38f;

    float m = sv;
#pragma unroll
    for (int o = 16; o > 0; o >>= 1) m = fmaxf(m, __shfl_xor_sync(0xffffffffu, m, o));
    if ((t & 31) == 0) red[t >> 5] = m;
    __syncthreads();
    if (t < 8) {
        m = red[t];
#pragma unroll
        for (int o = 4; o > 0; o >>= 1) m = fmaxf(m, __shfl_xor_sync(0xffu, m, o));
        if (t == 0) smax = m;
    }
    __syncthreads();

    float e = (t < TK) ? expf(sv - smax) : 0.f;
    float su = e;
#pragma unroll
    for (int o = 16; o > 0; o >>= 1) su += __shfl_xor_sync(0xffffffffu, su, o);
    if ((t & 31) == 0) red[t >> 5] = su;
    __syncthreads();
    if (t < 8) {
        su = red[t];
#pragma unroll
        for (int o = 4; o > 0; o >>= 1) su += __shfl_xor_sync(0xffu, su, o);
        if (t == 0) ssum = su;
    }
    __syncthreads();

    if (t < TK) {
        const float a = e / ssum;
        alpha[b * TK + t] = a;
        out[OUT_ALPHA + b * TK + t] = a;
        out[OUT_COV + b * TK + t] = cov[b * TK + t] + a;
    }
}

__global__ void __launch_bounds__(256) cimg_kernel(
    const float* __restrict__ gstar, const float* __restrict__ alpha,
    float* __restrict__ out)
{
    const int b = blockIdx.y;
    const int d = blockIdx.x * 256 + threadIdx.x;
    __shared__ float sal[TK];
    if (threadIdx.x < TK) sal[threadIdx.x] = alpha[b * TK + threadIdx.x];
    __syncthreads();
    float s = 0.f;
#pragma unroll 4
    for (int t = 0; t < TK; t++)
        s += sal[t] * gstar[((size_t)(b * TK + t)) * DH + d];
    out[OUT_C + b * DH + d] = s;
}

// ============================ launch ============================
extern "C" void kernel_launch(void* const* d_in, const int* in_sizes, int n_in,
                              void* d_out, int out_size)
{
    const float* gf   = (const float*)d_in[0];
    const float* sth  = (const float*)d_in[1];
    const float* cov  = (const float*)d_in[2];
    const float* Wg   = (const float*)d_in[3];
    const float* bg   = (const float*)d_in[4];
    const float* Gs   = (const float*)d_in[5];
    const float* bgs  = (const float*)d_in[6];
    const float* Wgs  = (const float*)d_in[7];
    const float* Wdec = (const float*)d_in[8];
    const float* bdec = (const float*)d_in[9];
    const float* v    = (const float*)d_in[10];
    float* out = (float*)d_out;

    __nv_bfloat16 *WgH, *WgL, *gfH, *gfL, *GsTH, *GsTL, *W2TH, *W2TL, *WgsTH, *WgsTL, *gsH, *gsL;
    float *W2p, *gstarp, *b2p, *decp, *scoresp, *alphap;
    cudaGetSymbolAddress((void**)&WgH, g_WgH);     cudaGetSymbolAddress((void**)&WgL, g_WgL);
    cudaGetSymbolAddress((void**)&gfH, g_gfH);     cudaGetSymbolAddress((void**)&gfL, g_gfL);
    cudaGetSymbolAddress((void**)&GsTH, g_GsTH);   cudaGetSymbolAddress((void**)&GsTL, g_GsTL);
    cudaGetSymbolAddress((void**)&W2p, g_W2);
    cudaGetSymbolAddress((void**)&W2TH, g_W2TH);   cudaGetSymbolAddress((void**)&W2TL, g_W2TL);
    cudaGetSymbolAddress((void**)&WgsTH, g_WgsTH); cudaGetSymbolAddress((void**)&WgsTL, g_WgsTL);
    cudaGetSymbolAddress((void**)&gstarp, g_gstar);
    cudaGetSymbolAddress((void**)&gsH, g_gsH);     cudaGetSymbolAddress((void**)&gsL, g_gsL);
    cudaGetSymbolAddress((void**)&b2p, g_b2);      cudaGetSymbolAddress((void**)&decp, g_dec);
    cudaGetSymbolAddress((void**)&scoresp, g_scores);
    cudaGetSymbolAddress((void**)&alphap, g_alpha);

    cudaFuncSetAttribute(gemm_mma, cudaFuncAttributeMaxDynamicSharedMemorySize, GEMM_SMEM);

    // (0) split Wg
    csplit<<<(GFD * GFD / 4 + 255) / 256, 256>>>((const float4*)Wg,
        (__nv_bfloat162*)WgH, (__nv_bfloat162*)WgL, GFD * GFD / 4);
    // (1) transpose+split Gs
    {   dim3 g(DH / 32, GFD / 32);  tconv<<<g, 256>>>(Gs, GsTH, GsTL, GFD, DH); }
    // (2) b2 = bg @ Gs + bgs
    b2_kernel<<<DH / 256, 256>>>(bg, Gs, bgs, b2p);
    // (3) GEMM1: W2 = Wg @ Gs   [4096,1024], K=4096
    {
        dim3 grid(DH / 64, GFD / 128);
        gemm_mma<<<grid, 128, GEMM_SMEM>>>(WgH, WgL, GsTH, GsTL, GFD, GFD / KTILE, 0,
            W2p, nullptr, nullptr, nullptr, nullptr, nullptr, nullptr, nullptr);
    }
    // (4) split gf
    csplit<<<(BT * GFD / 4 + 255) / 256, 256>>>((const float4*)gf,
        (__nv_bfloat162*)gfH, (__nv_bfloat162*)gfL, BT * GFD / 4);
    // (5) transpose+split W2
    {   dim3 g(DH / 32, GFD / 32);  tconv<<<g, 256>>>(W2p, W2TH, W2TL, GFD, DH); }
    // (6) GEMM2: g_star = gf @ W2 + b2   [6272,1024], K=4096
    {
        dim3 grid(DH / 64, BT / 128);
        gemm_mma<<<grid, 128, GEMM_SMEM>>>(gfH, gfL, W2TH, W2TL, GFD, GFD / KTILE, 1,
            gstarp, b2p, gsH, gsL, nullptr, nullptr, nullptr, nullptr);
    }
    // (7) transpose+split Wgs
    {   dim3 g(DH / 32, DH / 32);   tconv<<<g, 256>>>(Wgs, WgsTH, WgsTL, DH, DH); }
    // (8) dec = s_t_hat @ Wdec + bdec
    dec_kernel<<<(BATCH * DH) / 256, 256>>>(sth, Wdec, bdec, decp);
    // (9) zero scores
    cudaMemsetAsync(scoresp, 0, BT * sizeof(float));
    // (10) GEMM3 (fused): scores = tanh(g_star@Wgs + dec + cov) . v   K=1024
    {
        dim3 grid(DH / 64, BT / 128);
        gemm_mma<<<grid, 128, GEMM_SMEM>>>(gsH, gsL, WgsTH, WgsTL, DH, DH / KTILE, 2,
            nullptr, nullptr, nullptr, nullptr, decp, cov, v, scoresp);
    }
    // (11) softmax + outputs
    softmax_kernel<<<BATCH, 256>>>(scoresp, cov, alphap, out);
    // (12) context vector
    {   dim3 grid(DH / 256, BATCH);  cimg_kernel<<<grid, 256>>>(gstarp, alphap, out); }
}